// round 4
// baseline (speedup 1.0000x reference)
#include <cuda_runtime.h>

// Problem constants
#define BB   512
#define TT   65536
#define CL   128                  // chunk length
#define NC   (TT / CL)            // 512 chunks per row
#define NTH  256
#define NRP  (BB / 2)             // 256 row pairs
#define GRID (NRP * 2)            // 512 blocks (2 half-rows of chunks per row pair)

// smem layout: [0,2560) five 8x8 matrices as duplicated float2; then 2 staging
// buffers of NTH*9 float4 (one per row of the pair), used in-place for output.
#define MATS_BYTES 2560
#define BUF_F4     (NTH * 9)
#define SMEM_TOT   (MATS_BYTES + 2 * BUF_F4 * 16)   // 2560 + 73728 = 76288

typedef unsigned long long u64f;

// Scratch (static __device__ arrays -- no allocation)
__device__ __align__(16) float g_y1[(size_t)BB * TT];        // forward output (128 MB)
__device__ __align__(16) u64f  g_v [(size_t)NRP * NC * 8];   // fwd chunk states (packed rows)
__device__ __align__(16) u64f  g_vb[(size_t)NRP * NC * 8];   // bwd chunk states (packed rows)
__device__ float g_coef[17];    // [0..8]=b/a0, [9..16]=-(a[1..8]/a0)
__device__ float g_mats[320];   // A32 | A64 | A96 | A128(M) | A256(M2), row-major 8x8

// ---------------------------------------------------------------------------
// Packed float2 helpers
// ---------------------------------------------------------------------------
#define FFMA2(d, a, b, c) asm("fma.rn.f32x2 %0, %1, %2, %3;" : "=l"(d) : "l"(a), "l"(b), "l"(c))

__device__ __forceinline__ u64f pk2(float lo, float hi) {
    u64f r; asm("mov.b64 %0, {%1, %2};" : "=l"(r) : "f"(lo), "f"(hi)); return r;
}
__device__ __forceinline__ float2 upk(u64f v) {
    float2 r; asm("mov.b64 {%0, %1}, %2;" : "=f"(r.x), "=f"(r.y) : "l"(v)); return r;
}

// One packed DF2T step on state z[8]; returns packed y. Fully unrolled -> regs.
__device__ __forceinline__ u64f pstep(u64f x, u64f* z, const u64f* cb, const u64f* cna) {
    u64f y, t;
    FFMA2(y, cb[0], x, z[0]);
    #pragma unroll
    for (int i = 0; i < 7; i++) {
        FFMA2(t, cb[i + 1], x, z[i + 1]);
        FFMA2(z[i], cna[i], y, t);
    }
    u64f zz = 0ULL;
    FFMA2(t, cb[8], x, zz);
    FFMA2(z[7], cna[7], y, t);
    return y;
}

#define LOAD_COEF_PK()                                         \
    u64f cb[9], cna[8];                                        \
    _Pragma("unroll")                                          \
    for (int i_ = 0; i_ < 9; i_++) { float c_ = g_coef[i_];    \
        cb[i_] = pk2(c_, c_); }                                \
    _Pragma("unroll")                                          \
    for (int i_ = 0; i_ < 8; i_++) { float c_ = g_coef[9 + i_];\
        cna[i_] = pk2(c_, c_); }

// Conditional 8-vector load helper (avoids pragma-in-brace issues)
__device__ __forceinline__ void load_v8(u64f* dst, const u64f* src, bool pred) {
    #pragma unroll
    for (int i = 0; i < 8; i++) dst[i] = pred ? src[i] : 0ULL;
}

// ---------------------------------------------------------------------------
// Setup: normalize coefficients; build A32 and its powers A64, A96, A128, A256.
// ---------------------------------------------------------------------------
__global__ void setup_kernel(const float* __restrict__ b, const float* __restrict__ a) {
    __shared__ float sa[9];
    __shared__ float P32[64], P64[64], P96[64], P128[64];
    int tid = threadIdx.x;
    if (tid == 0) {
        float inv = 1.0f / a[0];
        #pragma unroll
        for (int i = 0; i < 9; i++) {
            float bn = b[i] * inv;
            float an = a[i] * inv;
            g_coef[i] = bn;
            if (i >= 1) g_coef[8 + i] = -an;
            sa[i] = an;
        }
    }
    __syncthreads();
    if (tid < 8) {
        float s[9];
        #pragma unroll
        for (int i = 0; i < 9; i++) s[i] = 0.0f;
        s[tid] = 1.0f;
        for (int step = 0; step < 32; step++) {
            float y = s[0];
            #pragma unroll
            for (int i = 0; i < 8; i++) s[i] = s[i + 1] - sa[i + 1] * y;
        }
        #pragma unroll
        for (int i = 0; i < 8; i++) P32[i * 8 + tid] = s[i];
    }
    __syncthreads();
    int i = tid >> 3, j = tid & 7;
    float acc;
    acc = 0.0f;
    #pragma unroll
    for (int k = 0; k < 8; k++) acc = fmaf(P32[i * 8 + k], P32[k * 8 + j], acc);
    P64[tid] = acc; __syncthreads();
    acc = 0.0f;
    #pragma unroll
    for (int k = 0; k < 8; k++) acc = fmaf(P64[i * 8 + k], P32[k * 8 + j], acc);
    P96[tid] = acc; __syncthreads();
    acc = 0.0f;
    #pragma unroll
    for (int k = 0; k < 8; k++) acc = fmaf(P96[i * 8 + k], P32[k * 8 + j], acc);
    P128[tid] = acc; __syncthreads();
    acc = 0.0f;
    #pragma unroll
    for (int k = 0; k < 8; k++) acc = fmaf(P128[i * 8 + k], P128[k * 8 + j], acc);
    g_mats[tid]       = P32[tid];
    g_mats[64 + tid]  = P64[tid];
    g_mats[128 + tid] = P96[tid];
    g_mats[192 + tid] = P128[tid];
    g_mats[256 + tid] = acc;
}

// Lookback: z = v[c-1] + M*v[c-2] + M2*v[c-3] (packed), mats in smem (dup'd float2)
__device__ __forceinline__ void lookback(u64f* z, const u64f* vrow, int c, const float2* mats) {
    u64f v1[8], v2[8], v3[8];
    load_v8(v1, vrow + (c - 1) * 8, c >= 1);
    load_v8(v2, vrow + (c - 2) * 8, c >= 2);
    load_v8(v3, vrow + (c - 3) * 8, c >= 3);
    #pragma unroll
    for (int i = 0; i < 8; i++) {
        u64f acc = v1[i];
        #pragma unroll
        for (int j = 0; j < 8; j++) {
            u64f m = *(const u64f*)(mats + 192 + i * 8 + j);
            FFMA2(acc, m, v2[j], acc);
        }
        #pragma unroll
        for (int j = 0; j < 8; j++) {
            u64f m = *(const u64f*)(mats + 256 + i * 8 + j);
            FFMA2(acc, m, v3[j], acc);
        }
        z[i] = acc;
    }
}

// ---------------------------------------------------------------------------
// fstate: forward zero-state chunk filtering (2 rows packed); emit final states.
// ---------------------------------------------------------------------------
__global__ void __launch_bounds__(NTH) fstate_k(const float* __restrict__ x,
                                                u64f* __restrict__ vout) {
    extern __shared__ char smc[];
    float4* b0 = (float4*)(smc + MATS_BYTES);
    float4* b1 = b0 + BUF_F4;

    int rp = blockIdx.x >> 1, h = blockIdx.x & 1, t = threadIdx.x;
    const float* p0 = x + (size_t)(rp * 2) * TT;
    const float* p1 = p0 + TT;

    LOAD_COEF_PK();
    u64f z[8];
    #pragma unroll
    for (int i2 = 0; i2 < 8; i2++) z[i2] = 0ULL;

    #pragma unroll 1
    for (int s = 0; s < 4; s++) {
        #pragma unroll
        for (int l = 0; l < 8; l++) {
            int q = l * NTH + t;
            int tt = q >> 3, j = q & 7;
            int base = h * 32768 + tt * CL + s * 32 + 4 * j;
            b0[tt * 9 + j] = *reinterpret_cast<const float4*>(p0 + base);
            b1[tt * 9 + j] = *reinterpret_cast<const float4*>(p1 + base);
        }
        __syncthreads();
        #pragma unroll
        for (int j2 = 0; j2 < 8; j2++) {
            float4 a4 = b0[t * 9 + j2];
            float4 c4 = b1[t * 9 + j2];
            pstep(pk2(a4.x, c4.x), z, cb, cna);
            pstep(pk2(a4.y, c4.y), z, cb, cna);
            pstep(pk2(a4.z, c4.z), z, cb, cna);
            pstep(pk2(a4.w, c4.w), z, cb, cna);
        }
        __syncthreads();
    }
    int c = h * 256 + t;
    u64f* vp = vout + ((size_t)rp * NC + c) * 8;
    #pragma unroll
    for (int i2 = 0; i2 < 8; i2++) vp[i2] = z[i2];
}

// ---------------------------------------------------------------------------
// fout: seeded forward filtering; writes y1 AND computes backward chunk states
// v_b = w0 + A32*w1 + A64*w2 + A96*w3 from the freshly produced y (fused).
// ---------------------------------------------------------------------------
__global__ void __launch_bounds__(NTH) fout_k(const float* __restrict__ x,
                                              float* __restrict__ y1,
                                              const u64f* __restrict__ vin,
                                              u64f* __restrict__ vbout) {
    extern __shared__ char smc[];
    float2* mats = (float2*)smc;
    float4* b0 = (float4*)(smc + MATS_BYTES);
    float4* b1 = b0 + BUF_F4;

    int t = threadIdx.x;
    for (int k = t; k < 320; k += NTH) { float mv = g_mats[k]; mats[k] = make_float2(mv, mv); }

    int rp = blockIdx.x >> 1, h = blockIdx.x & 1;
    int c = h * 256 + t;
    const float* p0 = x + (size_t)(rp * 2) * TT;
    const float* p1 = p0 + TT;
    float* o0 = y1 + (size_t)(rp * 2) * TT;
    float* o1 = o0 + TT;

    __syncthreads();   // mats ready
    u64f z[8];
    lookback(z, vin + (size_t)rp * NC * 8, c, mats);

    LOAD_COEF_PK();
    u64f va[8];
    #pragma unroll
    for (int i2 = 0; i2 < 8; i2++) va[i2] = 0ULL;

    #pragma unroll 1
    for (int s = 0; s < 4; s++) {
        #pragma unroll
        for (int l = 0; l < 8; l++) {
            int q = l * NTH + t;
            int tt = q >> 3, j = q & 7;
            int base = h * 32768 + tt * CL + s * 32 + 4 * j;
            b0[tt * 9 + j] = *reinterpret_cast<const float4*>(p0 + base);
            b1[tt * 9 + j] = *reinterpret_cast<const float4*>(p1 + base);
        }
        __syncthreads();
        // produce y in-place
        #pragma unroll
        for (int j2 = 0; j2 < 8; j2++) {
            float4 a4 = b0[t * 9 + j2];
            float4 c4 = b1[t * 9 + j2];
            float2 y0 = upk(pstep(pk2(a4.x, c4.x), z, cb, cna));
            float2 y1v = upk(pstep(pk2(a4.y, c4.y), z, cb, cna));
            float2 y2v = upk(pstep(pk2(a4.z, c4.z), z, cb, cna));
            float2 y3v = upk(pstep(pk2(a4.w, c4.w), z, cb, cna));
            b0[t * 9 + j2] = make_float4(y0.x, y1v.x, y2v.x, y3v.x);
            b1[t * 9 + j2] = make_float4(y0.y, y1v.y, y2v.y, y3v.y);
        }
        // backward zero-state response of this (reversed) stage from own slots
        u64f w[8];
        #pragma unroll
        for (int i2 = 0; i2 < 8; i2++) w[i2] = 0ULL;
        #pragma unroll
        for (int j2 = 7; j2 >= 0; j2--) {
            float4 a4 = b0[t * 9 + j2];
            float4 c4 = b1[t * 9 + j2];
            pstep(pk2(a4.w, c4.w), w, cb, cna);
            pstep(pk2(a4.z, c4.z), w, cb, cna);
            pstep(pk2(a4.y, c4.y), w, cb, cna);
            pstep(pk2(a4.x, c4.x), w, cb, cna);
        }
        if (s == 0) {
            #pragma unroll
            for (int i2 = 0; i2 < 8; i2++) va[i2] = w[i2];
        } else {
            int mb = (s - 1) * 64;
            #pragma unroll
            for (int i2 = 0; i2 < 8; i2++) {
                u64f acc = va[i2];
                #pragma unroll
                for (int j2 = 0; j2 < 8; j2++) {
                    u64f m = *(const u64f*)(mats + mb + i2 * 8 + j2);
                    FFMA2(acc, m, w[j2], acc);
                }
                va[i2] = acc;
            }
        }
        __syncthreads();
        #pragma unroll
        for (int l = 0; l < 8; l++) {
            int q = l * NTH + t;
            int tt = q >> 3, j = q & 7;
            int base = h * 32768 + tt * CL + s * 32 + 4 * j;
            *reinterpret_cast<float4*>(o0 + base) = b0[tt * 9 + j];
            *reinterpret_cast<float4*>(o1 + base) = b1[tt * 9 + j];
        }
        __syncthreads();
    }
    // store backward chunk state at logical backward index NC-1-c
    u64f* vp = vbout + ((size_t)rp * NC + (NC - 1 - c)) * 8;
    #pragma unroll
    for (int i2 = 0; i2 < 8; i2++) vp[i2] = va[i2];
}

// ---------------------------------------------------------------------------
// bout: seeded backward filtering over y1 (reversed traversal), writes d_out.
// ---------------------------------------------------------------------------
__global__ void __launch_bounds__(NTH) bout_k(const float* __restrict__ y1,
                                              float* __restrict__ out,
                                              const u64f* __restrict__ vbin) {
    extern __shared__ char smc[];
    float2* mats = (float2*)smc;
    float4* b0 = (float4*)(smc + MATS_BYTES);
    float4* b1 = b0 + BUF_F4;

    int t = threadIdx.x;
    for (int k = t; k < 320; k += NTH) { float mv = g_mats[k]; mats[k] = make_float2(mv, mv); }

    int rp = blockIdx.x >> 1, h = blockIdx.x & 1;
    int c = h * 256 + t;   // logical backward chunk index
    const float* p0 = y1 + (size_t)(rp * 2) * TT;
    const float* p1 = p0 + TT;
    float* o0 = out + (size_t)(rp * 2) * TT;
    float* o1 = o0 + TT;

    __syncthreads();
    u64f z[8];
    lookback(z, vbin + (size_t)rp * NC * 8, c, mats);

    LOAD_COEF_PK();

    #pragma unroll 1
    for (int s = 0; s < 4; s++) {
        #pragma unroll
        for (int l = 0; l < 8; l++) {
            int q = l * NTH + t;
            int tq = q >> 3, j = q & 7;
            int tt = 255 - tq;
            int base = TT - (h * 256 + tt + 1) * CL + (3 - s) * 32 + 4 * j;
            b0[tt * 9 + j] = *reinterpret_cast<const float4*>(p0 + base);
            b1[tt * 9 + j] = *reinterpret_cast<const float4*>(p1 + base);
        }
        __syncthreads();
        #pragma unroll
        for (int j2 = 0; j2 < 8; j2++) {
            float4 a4 = b0[t * 9 + (7 - j2)];
            float4 c4 = b1[t * 9 + (7 - j2)];
            float2 y0 = upk(pstep(pk2(a4.w, c4.w), z, cb, cna));
            float2 y1v = upk(pstep(pk2(a4.z, c4.z), z, cb, cna));
            float2 y2v = upk(pstep(pk2(a4.y, c4.y), z, cb, cna));
            float2 y3v = upk(pstep(pk2(a4.x, c4.x), z, cb, cna));
            b0[t * 9 + (7 - j2)] = make_float4(y3v.x, y2v.x, y1v.x, y0.x);
            b1[t * 9 + (7 - j2)] = make_float4(y3v.y, y2v.y, y1v.y, y0.y);
        }
        __syncthreads();
        #pragma unroll
        for (int l = 0; l < 8; l++) {
            int q = l * NTH + t;
            int tq = q >> 3, j = q & 7;
            int tt = 255 - tq;
            int base = TT - (h * 256 + tt + 1) * CL + (3 - s) * 32 + 4 * j;
            *reinterpret_cast<float4*>(o0 + base) = b0[tt * 9 + j];
            *reinterpret_cast<float4*>(o1 + base) = b1[tt * 9 + j];
        }
        __syncthreads();
    }
}

extern "C" void kernel_launch(void* const* d_in, const int* in_sizes, int n_in,
                              void* d_out, int out_size) {
    const float* x = (const float*)d_in[0];
    const float* b = (const float*)d_in[1];
    const float* a = (const float*)d_in[2];
    float* out = (float*)d_out;

    float* py1 = nullptr;
    u64f *pv = nullptr, *pvb = nullptr;
    cudaGetSymbolAddress((void**)&py1, g_y1);
    cudaGetSymbolAddress((void**)&pv,  g_v);
    cudaGetSymbolAddress((void**)&pvb, g_vb);

    static bool attr_done = false;
    if (!attr_done) {
        cudaFuncSetAttribute(fstate_k, cudaFuncAttributeMaxDynamicSharedMemorySize, SMEM_TOT);
        cudaFuncSetAttribute(fout_k,   cudaFuncAttributeMaxDynamicSharedMemorySize, SMEM_TOT);
        cudaFuncSetAttribute(bout_k,   cudaFuncAttributeMaxDynamicSharedMemorySize, SMEM_TOT);
        attr_done = true;
    }

    setup_kernel<<<1, 64>>>(b, a);
    fstate_k<<<GRID, NTH, SMEM_TOT>>>(x, pv);
    fout_k<<<GRID, NTH, SMEM_TOT>>>(x, py1, pv, pvb);
    bout_k<<<GRID, NTH, SMEM_TOT>>>(py1, out, pvb);
}

// round 5
// speedup vs baseline: 1.0201x; 1.0201x over previous
#include <cuda_runtime.h>

// Problem constants
#define BB   512
#define TT   65536
#define CL   128                  // chunk length
#define NC   (TT / CL)            // 512 chunks per row
#define NTH  512                  // one thread per chunk; block = one row PAIR
#define GRID (BB / 2)             // 256 blocks

typedef unsigned long long u64f;

// smem byte offsets
#define OFF_MATS 0                          // 320 float2 (duplicated 8x8 mats)
#define OFF_V    2560                       // 512*8 u64  = 32768
#define OFF_VA   35328                      // 512*8 u64  = 32768
#define OFF_B0   68096                      // 512*9 float4 = 73728
#define OFF_B1   141824                     // 512*9 float4 = 73728
#define SMEM_TOT 215552

// Scratch
__device__ __align__(16) float g_y1[(size_t)BB * TT];   // forward output (128 MB)
__device__ float g_coef[17];    // [0..8]=b/a0, [9..16]=-(a[1..8]/a0)
__device__ float g_mats[320];   // A32 | A64 | A96 | A128 | A256, row-major 8x8

// ---------------------------------------------------------------------------
#define FFMA2(d, a, b, c) asm("fma.rn.f32x2 %0, %1, %2, %3;" : "=l"(d) : "l"(a), "l"(b), "l"(c))

__device__ __forceinline__ u64f pk2(float lo, float hi) {
    u64f r; asm("mov.b64 %0, {%1, %2};" : "=l"(r) : "f"(lo), "f"(hi)); return r;
}
__device__ __forceinline__ float2 upk(u64f v) {
    float2 r; asm("mov.b64 {%0, %1}, %2;" : "=f"(r.x), "=f"(r.y) : "l"(v)); return r;
}

__device__ __forceinline__ u64f pstep(u64f x, u64f* z, const u64f* cb, const u64f* cna) {
    u64f y, t;
    FFMA2(y, cb[0], x, z[0]);
    #pragma unroll
    for (int i = 0; i < 7; i++) {
        FFMA2(t, cb[i + 1], x, z[i + 1]);
        FFMA2(z[i], cna[i], y, t);
    }
    u64f zz = 0ULL;
    FFMA2(t, cb[8], x, zz);
    FFMA2(z[7], cna[7], y, t);
    return y;
}

#define LOAD_COEF_PK()                                         \
    u64f cb[9], cna[8];                                        \
    _Pragma("unroll")                                          \
    for (int i_ = 0; i_ < 9; i_++) { float c_ = g_coef[i_];    \
        cb[i_] = pk2(c_, c_); }                                \
    _Pragma("unroll")                                          \
    for (int i_ = 0; i_ < 8; i_++) { float c_ = g_coef[9 + i_];\
        cna[i_] = pk2(c_, c_); }

__device__ __forceinline__ void load_v8s(u64f* dst, const u64f* src, bool pred) {
    #pragma unroll
    for (int i = 0; i < 8; i++) dst[i] = pred ? src[i] : 0ULL;
}

// Lookback: z = v[c-1] + A128*v[c-2] + A256*v[c-3] (smem v, smem mats)
__device__ __forceinline__ void lookback(u64f* z, const u64f* vrow, int c, const float2* mats) {
    u64f v1[8], v2[8], v3[8];
    load_v8s(v1, vrow + (c - 1) * 8, c >= 1);
    load_v8s(v2, vrow + (c - 2) * 8, c >= 2);
    load_v8s(v3, vrow + (c - 3) * 8, c >= 3);
    #pragma unroll
    for (int i = 0; i < 8; i++) {
        u64f acc = v1[i];
        #pragma unroll
        for (int j = 0; j < 8; j++) {
            u64f m = *(const u64f*)(mats + 192 + i * 8 + j);
            FFMA2(acc, m, v2[j], acc);
        }
        #pragma unroll
        for (int j = 0; j < 8; j++) {
            u64f m = *(const u64f*)(mats + 256 + i * 8 + j);
            FFMA2(acc, m, v3[j], acc);
        }
        z[i] = acc;
    }
}

// ---------------------------------------------------------------------------
// Setup: normalize coefficients; build A32 and powers.
// ---------------------------------------------------------------------------
__global__ void setup_kernel(const float* __restrict__ b, const float* __restrict__ a) {
    __shared__ float sa[9];
    __shared__ float P32[64], P64[64], P96[64], P128[64];
    int tid = threadIdx.x;
    if (tid == 0) {
        float inv = 1.0f / a[0];
        #pragma unroll
        for (int i = 0; i < 9; i++) {
            float bn = b[i] * inv;
            float an = a[i] * inv;
            g_coef[i] = bn;
            if (i >= 1) g_coef[8 + i] = -an;
            sa[i] = an;
        }
    }
    __syncthreads();
    if (tid < 8) {
        float s[9];
        #pragma unroll
        for (int i = 0; i < 9; i++) s[i] = 0.0f;
        s[tid] = 1.0f;
        for (int step = 0; step < 32; step++) {
            float y = s[0];
            #pragma unroll
            for (int i = 0; i < 8; i++) s[i] = s[i + 1] - sa[i + 1] * y;
        }
        #pragma unroll
        for (int i = 0; i < 8; i++) P32[i * 8 + tid] = s[i];
    }
    __syncthreads();
    int i = tid >> 3, j = tid & 7;
    float acc;
    acc = 0.0f;
    #pragma unroll
    for (int k = 0; k < 8; k++) acc = fmaf(P32[i * 8 + k], P32[k * 8 + j], acc);
    P64[tid] = acc; __syncthreads();
    acc = 0.0f;
    #pragma unroll
    for (int k = 0; k < 8; k++) acc = fmaf(P64[i * 8 + k], P32[k * 8 + j], acc);
    P96[tid] = acc; __syncthreads();
    acc = 0.0f;
    #pragma unroll
    for (int k = 0; k < 8; k++) acc = fmaf(P96[i * 8 + k], P32[k * 8 + j], acc);
    P128[tid] = acc; __syncthreads();
    acc = 0.0f;
    #pragma unroll
    for (int k = 0; k < 8; k++) acc = fmaf(P128[i * 8 + k], P128[k * 8 + j], acc);
    g_mats[tid]       = P32[tid];
    g_mats[64 + tid]  = P64[tid];
    g_mats[128 + tid] = P96[tid];
    g_mats[192 + tid] = P128[tid];
    g_mats[256 + tid] = acc;
}

// ---------------------------------------------------------------------------
// Fused kernel: one block per row pair; three phases with smem-resident states.
// ---------------------------------------------------------------------------
__global__ void __launch_bounds__(NTH, 1) fused_k(const float* __restrict__ x,
                                                  float* __restrict__ y1,
                                                  float* __restrict__ out) {
    extern __shared__ char smc[];
    float2* mats = (float2*)(smc + OFF_MATS);
    u64f*   sv   = (u64f*)(smc + OFF_V);
    u64f*   sva  = (u64f*)(smc + OFF_VA);
    float4* b0   = (float4*)(smc + OFF_B0);
    float4* b1   = (float4*)(smc + OFF_B1);

    int t = threadIdx.x;            // == chunk index c
    int rp = blockIdx.x;
    const float* p0 = x + (size_t)(rp * 2) * TT;
    const float* p1 = p0 + TT;
    float* q0 = y1 + (size_t)(rp * 2) * TT;
    float* q1 = q0 + TT;
    float* o0 = out + (size_t)(rp * 2) * TT;
    float* o1 = o0 + TT;

    for (int k = t; k < 320; k += NTH) { float mv = g_mats[k]; mats[k] = make_float2(mv, mv); }
    LOAD_COEF_PK();

    // ---------------- P1: forward zero-state chunk states -> smem v ----------
    {
        u64f z[8];
        #pragma unroll
        for (int i2 = 0; i2 < 8; i2++) z[i2] = 0ULL;
        #pragma unroll 1
        for (int s = 0; s < 4; s++) {
            #pragma unroll
            for (int l = 0; l < 8; l++) {
                int q = l * NTH + t;
                int tt = q >> 3, j = q & 7;
                int base = tt * CL + s * 32 + 4 * j;
                b0[tt * 9 + j] = *reinterpret_cast<const float4*>(p0 + base);
                b1[tt * 9 + j] = *reinterpret_cast<const float4*>(p1 + base);
            }
            __syncthreads();
            #pragma unroll
            for (int j2 = 0; j2 < 8; j2++) {
                float4 a4 = b0[t * 9 + j2];
                float4 c4 = b1[t * 9 + j2];
                pstep(pk2(a4.x, c4.x), z, cb, cna);
                pstep(pk2(a4.y, c4.y), z, cb, cna);
                pstep(pk2(a4.z, c4.z), z, cb, cna);
                pstep(pk2(a4.w, c4.w), z, cb, cna);
            }
            __syncthreads();
        }
        #pragma unroll
        for (int i2 = 0; i2 < 8; i2++) sv[t * 8 + i2] = z[i2];
    }
    __syncthreads();

    // ---------------- P2: seeded forward, write y1, build backward states ----
    {
        u64f z[8];
        lookback(z, sv, t, mats);
        u64f va[8];
        #pragma unroll
        for (int i2 = 0; i2 < 8; i2++) va[i2] = 0ULL;

        #pragma unroll 1
        for (int s = 0; s < 4; s++) {
            #pragma unroll
            for (int l = 0; l < 8; l++) {
                int q = l * NTH + t;
                int tt = q >> 3, j = q & 7;
                int base = tt * CL + s * 32 + 4 * j;
                b0[tt * 9 + j] = *reinterpret_cast<const float4*>(p0 + base);
                b1[tt * 9 + j] = *reinterpret_cast<const float4*>(p1 + base);
            }
            __syncthreads();
            #pragma unroll
            for (int j2 = 0; j2 < 8; j2++) {
                float4 a4 = b0[t * 9 + j2];
                float4 c4 = b1[t * 9 + j2];
                float2 y0 = upk(pstep(pk2(a4.x, c4.x), z, cb, cna));
                float2 y1v = upk(pstep(pk2(a4.y, c4.y), z, cb, cna));
                float2 y2v = upk(pstep(pk2(a4.z, c4.z), z, cb, cna));
                float2 y3v = upk(pstep(pk2(a4.w, c4.w), z, cb, cna));
                b0[t * 9 + j2] = make_float4(y0.x, y1v.x, y2v.x, y3v.x);
                b1[t * 9 + j2] = make_float4(y0.y, y1v.y, y2v.y, y3v.y);
            }
            // backward zero-state response of this reversed stage
            u64f w[8];
            #pragma unroll
            for (int i2 = 0; i2 < 8; i2++) w[i2] = 0ULL;
            #pragma unroll
            for (int j2 = 7; j2 >= 0; j2--) {
                float4 a4 = b0[t * 9 + j2];
                float4 c4 = b1[t * 9 + j2];
                pstep(pk2(a4.w, c4.w), w, cb, cna);
                pstep(pk2(a4.z, c4.z), w, cb, cna);
                pstep(pk2(a4.y, c4.y), w, cb, cna);
                pstep(pk2(a4.x, c4.x), w, cb, cna);
            }
            if (s == 0) {
                #pragma unroll
                for (int i2 = 0; i2 < 8; i2++) va[i2] = w[i2];
            } else {
                int mb = (s - 1) * 64;
                #pragma unroll
                for (int i2 = 0; i2 < 8; i2++) {
                    u64f acc = va[i2];
                    #pragma unroll
                    for (int j2 = 0; j2 < 8; j2++) {
                        u64f m = *(const u64f*)(mats + mb + i2 * 8 + j2);
                        FFMA2(acc, m, w[j2], acc);
                    }
                    va[i2] = acc;
                }
            }
            __syncthreads();
            #pragma unroll
            for (int l = 0; l < 8; l++) {
                int q = l * NTH + t;
                int tt = q >> 3, j = q & 7;
                int base = tt * CL + s * 32 + 4 * j;
                *reinterpret_cast<float4*>(q0 + base) = b0[tt * 9 + j];
                *reinterpret_cast<float4*>(q1 + base) = b1[tt * 9 + j];
            }
        }
        // store backward chunk state at backward index NC-1-t
        #pragma unroll
        for (int i2 = 0; i2 < 8; i2++) sva[(NC - 1 - t) * 8 + i2] = va[i2];
    }
    __syncthreads();

    // ---------------- P3: seeded backward over y1, write out ------------------
    {
        u64f z[8];
        lookback(z, sva, t, mats);

        #pragma unroll 1
        for (int s = 0; s < 4; s++) {
            #pragma unroll
            for (int l = 0; l < 8; l++) {
                int q = l * NTH + t;
                int tq = q >> 3, j = q & 7;
                int tt = (NTH - 1) - tq;
                int base = TT - (tt + 1) * CL + (3 - s) * 32 + 4 * j;
                b0[tt * 9 + j] = *reinterpret_cast<const float4*>(q0 + base);
                b1[tt * 9 + j] = *reinterpret_cast<const float4*>(q1 + base);
            }
            __syncthreads();
            #pragma unroll
            for (int j2 = 0; j2 < 8; j2++) {
                float4 a4 = b0[t * 9 + (7 - j2)];
                float4 c4 = b1[t * 9 + (7 - j2)];
                float2 y0 = upk(pstep(pk2(a4.w, c4.w), z, cb, cna));
                float2 y1v = upk(pstep(pk2(a4.z, c4.z), z, cb, cna));
                float2 y2v = upk(pstep(pk2(a4.y, c4.y), z, cb, cna));
                float2 y3v = upk(pstep(pk2(a4.x, c4.x), z, cb, cna));
                b0[t * 9 + (7 - j2)] = make_float4(y3v.x, y2v.x, y1v.x, y0.x);
                b1[t * 9 + (7 - j2)] = make_float4(y3v.y, y2v.y, y1v.y, y0.y);
            }
            __syncthreads();
            #pragma unroll
            for (int l = 0; l < 8; l++) {
                int q = l * NTH + t;
                int tq = q >> 3, j = q & 7;
                int tt = (NTH - 1) - tq;
                int base = TT - (tt + 1) * CL + (3 - s) * 32 + 4 * j;
                *reinterpret_cast<float4*>(o0 + base) = b0[tt * 9 + j];
                *reinterpret_cast<float4*>(o1 + base) = b1[tt * 9 + j];
            }
        }
    }
}

extern "C" void kernel_launch(void* const* d_in, const int* in_sizes, int n_in,
                              void* d_out, int out_size) {
    const float* x = (const float*)d_in[0];
    const float* b = (const float*)d_in[1];
    const float* a = (const float*)d_in[2];
    float* out = (float*)d_out;

    float* py1 = nullptr;
    cudaGetSymbolAddress((void**)&py1, g_y1);

    static bool attr_done = false;
    if (!attr_done) {
        cudaFuncSetAttribute(fused_k, cudaFuncAttributeMaxDynamicSharedMemorySize, SMEM_TOT);
        attr_done = true;
    }

    setup_kernel<<<1, 64>>>(b, a);
    fused_k<<<GRID, NTH, SMEM_TOT>>>(x, py1, out);
}

// round 6
// speedup vs baseline: 1.1177x; 1.0956x over previous
#include <cuda_runtime.h>

// Problem constants
#define BB   512
#define TT   65536
#define CL   128                  // chunk length
#define NC   (TT / CL)            // 512 chunks per row
#define NTH  256
#define NRP  (BB / 2)             // 256 row pairs
#define GRID (NRP * 2)            // 512 blocks (h-split: 256 chunks per block)

#define BUF_F4   (NTH * 9)
#define SMEM_STG (2 * BUF_F4 * 16)    // 73728 bytes: two padded float4 buffers

typedef unsigned long long u64f;

// Scratch (static __device__ arrays -- no allocation)
__device__ __align__(16) u64f g_y1t[(size_t)NRP * TT];      // transposed packed y1 (128 MB)
__device__ __align__(16) u64f g_v [(size_t)NRP * NC * 8];   // fwd chunk states
__device__ __align__(16) u64f g_vb[(size_t)NRP * NC * 8];   // bwd chunk states
__device__ float g_coef[17];    // [0..8]=b/a0, [9..16]=-(a[1..8]/a0)
__device__ float g_mats[320];   // A32 | A64 | A96 | A128 | A256, row-major 8x8

// ---------------------------------------------------------------------------
#define FFMA2(d, a, b, c) asm("fma.rn.f32x2 %0, %1, %2, %3;" : "=l"(d) : "l"(a), "l"(b), "l"(c))

__device__ __forceinline__ u64f pk2(float lo, float hi) {
    u64f r; asm("mov.b64 %0, {%1, %2};" : "=l"(r) : "f"(lo), "f"(hi)); return r;
}
__device__ __forceinline__ float2 upk(u64f v) {
    float2 r; asm("mov.b64 {%0, %1}, %2;" : "=f"(r.x), "=f"(r.y) : "l"(v)); return r;
}
__device__ __forceinline__ u64f pk2g(float v) { return pk2(v, v); }

__device__ __forceinline__ u64f pstep(u64f x, u64f* z, const u64f* cb, const u64f* cna) {
    u64f y, t;
    FFMA2(y, cb[0], x, z[0]);
    #pragma unroll
    for (int i = 0; i < 7; i++) {
        FFMA2(t, cb[i + 1], x, z[i + 1]);
        FFMA2(z[i], cna[i], y, t);
    }
    u64f zz = 0ULL;
    FFMA2(t, cb[8], x, zz);
    FFMA2(z[7], cna[7], y, t);
    return y;
}

#define LOAD_COEF_PK()                                         \
    u64f cb[9], cna[8];                                        \
    _Pragma("unroll")                                          \
    for (int i_ = 0; i_ < 9; i_++) { float c_ = g_coef[i_];    \
        cb[i_] = pk2(c_, c_); }                                \
    _Pragma("unroll")                                          \
    for (int i_ = 0; i_ < 8; i_++) { float c_ = g_coef[9 + i_];\
        cna[i_] = pk2(c_, c_); }

__device__ __forceinline__ void load_v8s(u64f* dst, const u64f* src, bool pred) {
    #pragma unroll
    for (int i = 0; i < 8; i++) dst[i] = pred ? src[i] : 0ULL;
}

// Lookback: z = v[c-1] + A128*v[c-2] + A256*v[c-3]; mats via uniform gmem loads.
__device__ __forceinline__ void lookback_g(u64f* z, const u64f* vrow, int c) {
    u64f v1[8], v2[8], v3[8];
    load_v8s(v1, vrow + (c - 1) * 8, c >= 1);
    load_v8s(v2, vrow + (c - 2) * 8, c >= 2);
    load_v8s(v3, vrow + (c - 3) * 8, c >= 3);
    #pragma unroll
    for (int i = 0; i < 8; i++) {
        u64f acc = v1[i];
        #pragma unroll
        for (int j = 0; j < 8; j++) {
            u64f m = pk2g(g_mats[192 + i * 8 + j]);
            FFMA2(acc, m, v2[j], acc);
        }
        #pragma unroll
        for (int j = 0; j < 8; j++) {
            u64f m = pk2g(g_mats[256 + i * 8 + j]);
            FFMA2(acc, m, v3[j], acc);
        }
        z[i] = acc;
    }
}

// ---------------------------------------------------------------------------
// Setup: normalize coefficients; build A32 and powers.
// ---------------------------------------------------------------------------
__global__ void setup_kernel(const float* __restrict__ b, const float* __restrict__ a) {
    __shared__ float sa[9];
    __shared__ float P32[64], P64[64], P96[64], P128[64];
    int tid = threadIdx.x;
    if (tid == 0) {
        float inv = 1.0f / a[0];
        #pragma unroll
        for (int i = 0; i < 9; i++) {
            float bn = b[i] * inv;
            float an = a[i] * inv;
            g_coef[i] = bn;
            if (i >= 1) g_coef[8 + i] = -an;
            sa[i] = an;
        }
    }
    __syncthreads();
    if (tid < 8) {
        float s[9];
        #pragma unroll
        for (int i = 0; i < 9; i++) s[i] = 0.0f;
        s[tid] = 1.0f;
        for (int step = 0; step < 32; step++) {
            float y = s[0];
            #pragma unroll
            for (int i = 0; i < 8; i++) s[i] = s[i + 1] - sa[i + 1] * y;
        }
        #pragma unroll
        for (int i = 0; i < 8; i++) P32[i * 8 + tid] = s[i];
    }
    __syncthreads();
    int i = tid >> 3, j = tid & 7;
    float acc;
    acc = 0.0f;
    #pragma unroll
    for (int k = 0; k < 8; k++) acc = fmaf(P32[i * 8 + k], P32[k * 8 + j], acc);
    P64[tid] = acc; __syncthreads();
    acc = 0.0f;
    #pragma unroll
    for (int k = 0; k < 8; k++) acc = fmaf(P64[i * 8 + k], P32[k * 8 + j], acc);
    P96[tid] = acc; __syncthreads();
    acc = 0.0f;
    #pragma unroll
    for (int k = 0; k < 8; k++) acc = fmaf(P96[i * 8 + k], P32[k * 8 + j], acc);
    P128[tid] = acc; __syncthreads();
    acc = 0.0f;
    #pragma unroll
    for (int k = 0; k < 8; k++) acc = fmaf(P128[i * 8 + k], P128[k * 8 + j], acc);
    g_mats[tid]       = P32[tid];
    g_mats[64 + tid]  = P64[tid];
    g_mats[128 + tid] = P96[tid];
    g_mats[192 + tid] = P128[tid];
    g_mats[256 + tid] = acc;
}

// ---------------------------------------------------------------------------
// fstate: forward zero-state chunk states (2 rows packed) -> g_v.
// ---------------------------------------------------------------------------
__global__ void __launch_bounds__(NTH, 3) fstate_k(const float* __restrict__ x,
                                                   u64f* __restrict__ vout) {
    extern __shared__ char smc[];
    float4* b0 = (float4*)smc;
    float4* b1 = b0 + BUF_F4;

    int rp = blockIdx.x >> 1, h = blockIdx.x & 1, t = threadIdx.x;
    const float* p0 = x + (size_t)(rp * 2) * TT;
    const float* p1 = p0 + TT;

    LOAD_COEF_PK();
    u64f z[8];
    #pragma unroll
    for (int i2 = 0; i2 < 8; i2++) z[i2] = 0ULL;

    #pragma unroll 1
    for (int s = 0; s < 4; s++) {
        #pragma unroll
        for (int l = 0; l < 8; l++) {
            int q = l * NTH + t;
            int tt = q >> 3, j = q & 7;
            int base = h * 32768 + tt * CL + s * 32 + 4 * j;
            b0[tt * 9 + j] = *reinterpret_cast<const float4*>(p0 + base);
            b1[tt * 9 + j] = *reinterpret_cast<const float4*>(p1 + base);
        }
        __syncthreads();
        #pragma unroll
        for (int j2 = 0; j2 < 8; j2++) {
            float4 a4 = b0[t * 9 + j2];
            float4 c4 = b1[t * 9 + j2];
            pstep(pk2(a4.x, c4.x), z, cb, cna);
            pstep(pk2(a4.y, c4.y), z, cb, cna);
            pstep(pk2(a4.z, c4.z), z, cb, cna);
            pstep(pk2(a4.w, c4.w), z, cb, cna);
        }
        __syncthreads();
    }
    int c = h * 256 + t;
    u64f* vp = vout + ((size_t)rp * NC + c) * 8;
    #pragma unroll
    for (int i2 = 0; i2 < 8; i2++) vp[i2] = z[i2];
}

// ---------------------------------------------------------------------------
// fout: seeded forward; writes y1T (transposed packed u64, inline coalesced
// STG.64) and the fused backward chunk states -> g_vb.
// ---------------------------------------------------------------------------
__global__ void __launch_bounds__(NTH, 2) fout_k(const float* __restrict__ x,
                                                 u64f* __restrict__ y1t,
                                                 const u64f* __restrict__ vin,
                                                 u64f* __restrict__ vbout) {
    extern __shared__ char smc[];
    float4* b0 = (float4*)smc;
    float4* b1 = b0 + BUF_F4;

    int rp = blockIdx.x >> 1, h = blockIdx.x & 1, t = threadIdx.x;
    int c = h * 256 + t;
    const float* p0 = x + (size_t)(rp * 2) * TT;
    const float* p1 = p0 + TT;
    u64f* yt = y1t + (size_t)rp * TT;

    u64f z[8];
    lookback_g(z, vin + (size_t)rp * NC * 8, c);

    LOAD_COEF_PK();
    u64f va[8];
    #pragma unroll
    for (int i2 = 0; i2 < 8; i2++) va[i2] = 0ULL;

    #pragma unroll 1
    for (int s = 0; s < 4; s++) {
        #pragma unroll
        for (int l = 0; l < 8; l++) {
            int q = l * NTH + t;
            int tt = q >> 3, j = q & 7;
            int base = h * 32768 + tt * CL + s * 32 + 4 * j;
            b0[tt * 9 + j] = *reinterpret_cast<const float4*>(p0 + base);
            b1[tt * 9 + j] = *reinterpret_cast<const float4*>(p1 + base);
        }
        __syncthreads();
        // forward filter; write y1T inline; keep y in smem for the w pass
        #pragma unroll
        for (int j2 = 0; j2 < 8; j2++) {
            float4 a4 = b0[t * 9 + j2];
            float4 c4 = b1[t * 9 + j2];
            u64f yp0 = pstep(pk2(a4.x, c4.x), z, cb, cna);
            u64f yp1 = pstep(pk2(a4.y, c4.y), z, cb, cna);
            u64f yp2 = pstep(pk2(a4.z, c4.z), z, cb, cna);
            u64f yp3 = pstep(pk2(a4.w, c4.w), z, cb, cna);
            int ibase = s * 32 + 4 * j2;
            yt[(ibase + 0) * NC + c] = yp0;
            yt[(ibase + 1) * NC + c] = yp1;
            yt[(ibase + 2) * NC + c] = yp2;
            yt[(ibase + 3) * NC + c] = yp3;
            float2 f0 = upk(yp0), f1 = upk(yp1), f2 = upk(yp2), f3 = upk(yp3);
            b0[t * 9 + j2] = make_float4(f0.x, f1.x, f2.x, f3.x);
            b1[t * 9 + j2] = make_float4(f0.y, f1.y, f2.y, f3.y);
        }
        // backward zero-state response of this reversed stage (own-thread smem)
        u64f w[8];
        #pragma unroll
        for (int i2 = 0; i2 < 8; i2++) w[i2] = 0ULL;
        #pragma unroll
        for (int j2 = 7; j2 >= 0; j2--) {
            float4 a4 = b0[t * 9 + j2];
            float4 c4 = b1[t * 9 + j2];
            pstep(pk2(a4.w, c4.w), w, cb, cna);
            pstep(pk2(a4.z, c4.z), w, cb, cna);
            pstep(pk2(a4.y, c4.y), w, cb, cna);
            pstep(pk2(a4.x, c4.x), w, cb, cna);
        }
        if (s == 0) {
            #pragma unroll
            for (int i2 = 0; i2 < 8; i2++) va[i2] = w[i2];
        } else {
            int mb = (s - 1) * 64;
            #pragma unroll
            for (int i2 = 0; i2 < 8; i2++) {
                u64f acc = va[i2];
                #pragma unroll
                for (int j2 = 0; j2 < 8; j2++) {
                    u64f m = pk2g(g_mats[mb + i2 * 8 + j2]);
                    FFMA2(acc, m, w[j2], acc);
                }
                va[i2] = acc;
            }
        }
        __syncthreads();
    }
    u64f* vp = vbout + ((size_t)rp * NC + (NC - 1 - c)) * 8;
    #pragma unroll
    for (int i2 = 0; i2 < 8; i2++) vp[i2] = va[i2];
}

// ---------------------------------------------------------------------------
// bout: seeded backward over y1T (direct coalesced LDG.64, no input staging);
// output staged to physical layout.
// ---------------------------------------------------------------------------
__global__ void __launch_bounds__(NTH, 3) bout_k(const u64f* __restrict__ y1t,
                                                 float* __restrict__ out,
                                                 const u64f* __restrict__ vbin) {
    extern __shared__ char smc[];
    float4* b0 = (float4*)smc;
    float4* b1 = b0 + BUF_F4;

    int rp = blockIdx.x >> 1, h = blockIdx.x & 1, t = threadIdx.x;
    int cbk = h * 256 + t;          // backward chunk index
    int c   = NC - 1 - cbk;         // original chunk index
    const u64f* yt = y1t + (size_t)rp * TT;
    float* o0 = out + (size_t)(rp * 2) * TT;
    float* o1 = o0 + TT;

    u64f z[8];
    lookback_g(z, vbin + (size_t)rp * NC * 8, cbk);

    LOAD_COEF_PK();

    #pragma unroll 1
    for (int s = 0; s < 4; s++) {
        // stage s covers original i in [96-32s, 128-32s), processed descending
        #pragma unroll
        for (int jj = 0; jj < 8; jj++) {
            int i3 = 127 - s * 32 - 4 * jj;       // top of the 4-group
            u64f x3 = yt[(size_t)(i3 - 0) * NC + c];
            u64f x2 = yt[(size_t)(i3 - 1) * NC + c];
            u64f x1 = yt[(size_t)(i3 - 2) * NC + c];
            u64f x0 = yt[(size_t)(i3 - 3) * NC + c];
            float2 y3 = upk(pstep(x3, z, cb, cna));   // output for i3
            float2 y2 = upk(pstep(x2, z, cb, cna));   // i3-1
            float2 y1v = upk(pstep(x1, z, cb, cna));  // i3-2
            float2 y0 = upk(pstep(x0, z, cb, cna));   // i3-3
            int jl = 7 - jj;                          // ascending-group slot
            b0[t * 9 + jl] = make_float4(y0.x, y1v.x, y2.x, y3.x);
            b1[t * 9 + jl] = make_float4(y0.y, y1v.y, y2.y, y3.y);
        }
        __syncthreads();
        #pragma unroll
        for (int l = 0; l < 8; l++) {
            int q = l * NTH + t;
            int tt = q >> 3, j = q & 7;
            int cc = NC - 1 - (h * 256 + tt);
            int base = cc * CL + (96 - 32 * s) + 4 * j;
            *reinterpret_cast<float4*>(o0 + base) = b0[tt * 9 + j];
            *reinterpret_cast<float4*>(o1 + base) = b1[tt * 9 + j];
        }
        __syncthreads();
    }
}

extern "C" void kernel_launch(void* const* d_in, const int* in_sizes, int n_in,
                              void* d_out, int out_size) {
    const float* x = (const float*)d_in[0];
    const float* b = (const float*)d_in[1];
    const float* a = (const float*)d_in[2];
    float* out = (float*)d_out;

    u64f *pyt = nullptr, *pv = nullptr, *pvb = nullptr;
    cudaGetSymbolAddress((void**)&pyt, g_y1t);
    cudaGetSymbolAddress((void**)&pv,  g_v);
    cudaGetSymbolAddress((void**)&pvb, g_vb);

    static bool attr_done = false;
    if (!attr_done) {
        cudaFuncSetAttribute(fstate_k, cudaFuncAttributeMaxDynamicSharedMemorySize, SMEM_STG);
        cudaFuncSetAttribute(fout_k,   cudaFuncAttributeMaxDynamicSharedMemorySize, SMEM_STG);
        cudaFuncSetAttribute(bout_k,   cudaFuncAttributeMaxDynamicSharedMemorySize, SMEM_STG);
        attr_done = true;
    }

    setup_kernel<<<1, 64>>>(b, a);
    fstate_k<<<GRID, NTH, SMEM_STG>>>(x, pv);
    fout_k<<<GRID, NTH, SMEM_STG>>>(x, pyt, pv, pvb);
    bout_k<<<GRID, NTH, SMEM_STG>>>(pyt, out, pvb);
}